// round 12
// baseline (speedup 1.0000x reference)
#include <cuda_runtime.h>
#include <cstdint>

#define N_   32
#define C_   256
#define O_   256
#define HW_  56
#define PIX  3136
#define NPIX (N_ * PIX)          // 100352 = 784 * 128
#define CNTS 802816.0f
#define EPSF 1e-5f

// ---------------- device scratch ----------------
__device__ float g_asum[N_];
__device__ float g_m[O_];
__device__ __align__(16) signed char g_xb[(size_t)NPIX * C_];     // int8 +-1 [pix][c]
__device__ __align__(16) signed char g_wb[9 * O_ * C_];           // int8 +-1 [tap][o][c]
__device__ __align__(16) unsigned g_xbits[(size_t)NPIX * 8];      // bitpacked [pix][8w]
__device__ __align__(16) unsigned g_wt[9 * 8 * O_];               // bitpacked [tap][w8][o]
__device__ int g_pw[O_ * 9];
__device__ int g_xz_count;
__device__ int g_wz_count;
__device__ int g_xz_list[4096];
__device__ int g_wz_list[64];

__device__ __forceinline__ float alpha_of(int n) {
    return fmaxf(2.f * g_asum[n] / CNTS, EPSF);
}

__device__ __forceinline__ void imma16832(int* c, const unsigned* a, const unsigned* b) {
    asm volatile(
        "mma.sync.aligned.m16n8k32.row.col.s32.s8.s8.s32 "
        "{%0,%1,%2,%3}, {%4,%5,%6,%7}, {%8,%9}, {%0,%1,%2,%3};"
        : "+r"(c[0]), "+r"(c[1]), "+r"(c[2]), "+r"(c[3])
        : "r"(a[0]), "r"(a[1]), "r"(a[2]), "r"(a[3]), "r"(b[0]), "r"(b[1]));
}

// ---------------- K0: zero everything ----------------
__global__ void k_zero() {
    int t = blockIdx.x * blockDim.x + threadIdx.x;
    if (t < N_) g_asum[t] = 0.f;
    if (t < O_ * 9) g_pw[t] = 0;
    if (t == 0) { g_xz_count = 0; g_wz_count = 0; }
}

// ---------------- K1: pack x -> int8 +-1 NHWC, bitpacked, sum|x|, zero list ----------
__global__ void k_packx(const float* __restrict__ x) {
    int b   = blockIdx.x;
    int n   = b & 31;
    int pix = (b >> 5) * 256 + threadIdx.x;
    int tid = threadIdx.x;

    float s = 0.f;
    if (pix < PIX) {
        const float* base = x + (size_t)n * C_ * PIX + pix;
        signed char* dst = &g_xb[((size_t)n * PIX + pix) * C_];
        unsigned bw[8];
#pragma unroll
        for (int w8 = 0; w8 < 8; w8++) {
            unsigned bb = 0;
            signed char u[32];
#pragma unroll
            for (int j = 0; j < 32; j++) {
                int ch = w8 * 32 + j;
                float v = base[(size_t)ch * PIX];
                s += fabsf(v);
                bool neg = (v < 0.f);
                u[j] = neg ? (signed char)-1 : (signed char)1;
                bb |= ((unsigned)neg) << j;
                if (v == 0.f) {
                    int idx = atomicAdd(&g_xz_count, 1);
                    if (idx < 4096) g_xz_list[idx] = (n * C_ + ch) * PIX + pix;
                }
            }
            bw[w8] = bb;
            *(uint4*)&dst[w8 * 32]      = *(const uint4*)&u[0];
            *(uint4*)&dst[w8 * 32 + 16] = *(const uint4*)&u[16];
        }
        uint4* bd = (uint4*)&g_xbits[((size_t)n * PIX + pix) * 8];
        bd[0] = make_uint4(bw[0], bw[1], bw[2], bw[3]);
        bd[1] = make_uint4(bw[4], bw[5], bw[6], bw[7]);
    }

    __shared__ float red[256];
    red[tid] = s;
    __syncthreads();
    for (int st = 128; st > 0; st >>= 1) {
        if (tid < st) red[tid] += red[tid + st];
        __syncthreads();
    }
    if (tid == 0) atomicAdd(&g_asum[n], red[0]);
}

// ---------------- K2: pack w ----------------
__global__ void k_packw(const float* __restrict__ w) {
    int o = blockIdx.x;
    int tid = threadIdx.x;
    int j = tid >> 5, lane = tid & 31;
    int c = j * 32 + lane;

    float s = 0.f;
#pragma unroll
    for (int tap = 0; tap < 9; tap++) {
        float v = w[((size_t)(o * C_ + c)) * 9 + tap];
        s += fabsf(v);
        bool neg = (v < 0.f);
        g_wb[((size_t)tap * O_ + o) * C_ + c] = neg ? (signed char)-1 : (signed char)1;
        unsigned bal = __ballot_sync(0xffffffffu, neg);
        if (lane == 0) {
            g_wt[(tap * 8 + j) * O_ + o] = bal;
            atomicAdd(&g_pw[o * 9 + tap], __popc(bal));
        }
        if (v == 0.f) {
            int idx = atomicAdd(&g_wz_count, 1);
            if (idx < 64) g_wz_list[idx] = (o * C_ + c) * 9 + tap;
        }
    }
    __shared__ float red[256];
    red[tid] = s;
    __syncthreads();
    for (int st = 128; st > 0; st >>= 1) {
        if (tid < st) red[tid] += red[tid + st];
        __syncthreads();
    }
    if (tid == 0) g_m[o] = red[0] / 2304.f;
}

// ---------------- K3: INTERLEAVED hybrid conv ----------------
// CTA 128(M) x 64(N); grid = 784 mtiles * 4 nquads = 3136; 256 thr, 8 warps (2Mx4N).
// Tensor: taps 0,1 (zero-halo exact). Popcount: taps 2..8, separate pacc, merged late.
// SMEM words: A8 128x36 | B8 64x36 | XB 7*8*128 | WB 7*8*64
#define RS8     36
#define B8_OFF  (128 * RS8)                 // 4608
#define XB_OFF  (B8_OFF + 64 * RS8)         // 6912
#define WB_OFF  (XB_OFF + 7 * 8 * 128)      // 14080
#define CONV_SMEM ((WB_OFF + 7 * 8 * 64) * 4)  // 70656 B

__global__ __launch_bounds__(256, 2) void k_conv(float* __restrict__ out) {
    extern __shared__ unsigned smw[];

    int tid  = threadIdx.x;
    int wid  = tid >> 5;
    int lane = tid & 31;
    int g    = lane >> 2;
    int tig  = lane & 3;

    int mBase = (blockIdx.x >> 2) * 128;
    int nBase = (blockIdx.x & 3) * 64;

    int m_off = (wid & 1) * 64;
    int n_off = (wid >> 1) * 16;

    int acc[4][2][4];    // IMMA accumulators (taps 0,1)
    int pacc[4][2][4];   // popcount accumulators (taps 2..8)
#pragma unroll
    for (int mi = 0; mi < 4; mi++)
#pragma unroll
        for (int ni = 0; ni < 2; ni++)
#pragma unroll
            for (int k = 0; k < 4; k++) { acc[mi][ni][k] = 0; pacc[mi][ni][k] = 0; }

    const uint4 z4 = make_uint4(0u, 0u, 0u, 0u);

    // ---- one-time fill of bitpacked tiles (taps 2..8) ----
    for (int u = tid; u < 7 * 128; u += 256) {
        int t7 = u >> 7, row = u & 127;
        int tap = t7 + 2;
        int gp = mBase + row;
        int fn = gp / PIX;
        int fp = gp - fn * PIX;
        int fh = fp / HW_, fw = fp - (fp / HW_) * HW_;
        int h2 = fh + tap / 3 - 1, w2 = fw + tap % 3 - 1;
        uint4 lo = z4, hi = z4;
        if ((unsigned)h2 < HW_ && (unsigned)w2 < HW_) {
            const uint4* src = (const uint4*)&g_xbits[((size_t)fn * PIX + h2 * HW_ + w2) * 8];
            lo = src[0]; hi = src[1];
        }
        unsigned* d = &smw[XB_OFF + t7 * 1024 + row];
        d[0] = lo.x; d[128] = lo.y; d[256] = lo.z; d[384] = lo.w;
        d[512] = hi.x; d[640] = hi.y; d[768] = hi.z; d[896] = hi.w;
    }
    for (int v = tid; v < 7 * 8 * 16; v += 256) {   // 896 uint4
        int q = v >> 4;                  // t7*8 + j
        int c4 = (v & 15) * 4;
        int t7 = q >> 3, j = q & 7;
        *(uint4*)&smw[WB_OFF + q * 64 + c4] =
            *(const uint4*)&g_wt[((t7 + 2) * 8 + j) * O_ + nBase + c4];
    }

    // fill-role mapping for int8 A tile
    int pix_i = tid >> 1;
    int half  = tid & 1;
    int gp = mBase + pix_i;
    int fn = gp / PIX;
    int fp = gp - fn * PIX;
    int fh = fp / HW_, fw = fp - (fp / HW_) * HW_;

    int pu = 0;   // popcount unit cursor 0..55

#pragma unroll 1
    for (int tt = 0; tt < 2; tt++) {
        int h2 = fh - 1, w2 = fw + tt - 1;
        bool valid = ((unsigned)h2 < HW_) && ((unsigned)w2 < HW_);
        const signed char* srcA = &g_xb[((size_t)fn * PIX + h2 * HW_ + w2) * C_];
#pragma unroll 1
        for (int hf = 0; hf < 2; hf++) {
            __syncthreads();
            {
                const uint4* sA = (const uint4*)(srcA + hf * 128 + half * 64);
#pragma unroll
                for (int j2 = 0; j2 < 4; j2++)
                    *(uint4*)&smw[pix_i * RS8 + half * 16 + j2 * 4] = valid ? sA[j2] : z4;
                if (tid < 128) {
                    int row = tid >> 1, bh = tid & 1;
                    const uint4* sB = (const uint4*)&g_wb[((size_t)tt * O_ + nBase + row) * C_ + hf * 128 + bh * 64];
#pragma unroll
                    for (int j2 = 0; j2 < 4; j2++)
                        *(uint4*)&smw[B8_OFF + row * RS8 + bh * 16 + j2 * 4] = sB[j2];
                }
            }
            __syncthreads();

#pragma unroll 1
            for (int kc = 0; kc < 4; kc++) {
                // ---- 8 IMMA ----
                unsigned a[4][4], bfr[2][2];
                int kw0 = kc * 8 + tig;
#pragma unroll
                for (int mi = 0; mi < 4; mi++) {
                    int base = (m_off + mi * 16 + g) * RS8 + kw0;
                    a[mi][0] = smw[base];
                    a[mi][1] = smw[base + 8 * RS8];
                    a[mi][2] = smw[base + 4];
                    a[mi][3] = smw[base + 8 * RS8 + 4];
                }
#pragma unroll
                for (int ni = 0; ni < 2; ni++) {
                    int base = B8_OFF + (n_off + ni * 8 + g) * RS8 + kw0;
                    bfr[ni][0] = smw[base];
                    bfr[ni][1] = smw[base + 4];
                }
#pragma unroll
                for (int mi = 0; mi < 4; mi++)
#pragma unroll
                    for (int ni = 0; ni < 2; ni++)
                        imma16832(acc[mi][ni], a[mi], bfr[ni]);

                // ---- 3-4 popcount units interleaved (independent pacc chain) ----
                int nu = (kc < 2) ? 4 : 3;
#pragma unroll 1
                for (int q = 0; q < nu; q++) {
                    const unsigned* xb = &smw[XB_OFF + pu * 128];
                    const unsigned* wb = &smw[WB_OFF + pu * 64];
                    unsigned xr[8], wc[4];
#pragma unroll
                    for (int mi = 0; mi < 4; mi++) {
                        xr[mi * 2]     = xb[m_off + mi * 16 + g];
                        xr[mi * 2 + 1] = xb[m_off + mi * 16 + 8 + g];
                    }
#pragma unroll
                    for (int ni = 0; ni < 2; ni++) {
                        wc[ni * 2]     = wb[n_off + ni * 8 + tig * 2];
                        wc[ni * 2 + 1] = wb[n_off + ni * 8 + tig * 2 + 1];
                    }
#pragma unroll
                    for (int mi = 0; mi < 4; mi++)
#pragma unroll
                        for (int ni = 0; ni < 2; ni++) {
                            pacc[mi][ni][0] += __popc(xr[mi * 2]     ^ wc[ni * 2]);
                            pacc[mi][ni][1] += __popc(xr[mi * 2]     ^ wc[ni * 2 + 1]);
                            pacc[mi][ni][2] += __popc(xr[mi * 2 + 1] ^ wc[ni * 2]);
                            pacc[mi][ni][3] += __popc(xr[mi * 2 + 1] ^ wc[ni * 2 + 1]);
                        }
                    pu++;
                }
            }
        }
    }

    // ---- epilogue: merge, pad-correct (taps 2..8), scale, store ----
#pragma unroll
    for (int mi = 0; mi < 4; mi++) {
#pragma unroll
        for (int h = 0; h < 2; h++) {
            int row = m_off + mi * 16 + h * 8 + g;
            int gpp = mBase + row;
            int n = gpp / PIX;
            int p = gpp - n * PIX;
            int oh = p / HW_, ow = p - (p / HW_) * HW_;
            float al = alpha_of(n);
            bool top = (oh == 0), bot = (oh == HW_ - 1);
            bool lef = (ow == 0), rig = (ow == HW_ - 1);
            bool edge = top || bot || lef || rig;
            float* ob = out + (size_t)n * O_ * PIX + p;
#pragma unroll
            for (int ni = 0; ni < 2; ni++) {
#pragma unroll
                for (int j = 0; j < 2; j++) {
                    int o = nBase + n_off + ni * 8 + tig * 2 + j;
                    int S = acc[mi][ni][h * 2 + j] + 1792 - 2 * pacc[mi][ni][h * 2 + j];
                    if (edge) {
                        const int* pwo = &g_pw[o * 9];
                        if (top || rig) S -= 256 - 2 * __ldg(pwo + 2);
                        if (lef)        S -= 256 - 2 * __ldg(pwo + 3);
                        if (rig)        S -= 256 - 2 * __ldg(pwo + 5);
                        if (bot || lef) S -= 256 - 2 * __ldg(pwo + 6);
                        if (bot)        S -= 256 - 2 * __ldg(pwo + 7);
                        if (bot || rig) S -= 256 - 2 * __ldg(pwo + 8);
                    }
                    ob[(size_t)o * PIX] = al * __ldg(&g_m[o]) * (float)S;
                }
            }
        }
    }
}

// ---------------- K4: exact correction for x==0 ----------------
__global__ void k_xzero(float* __restrict__ out) {
    int zc = g_xz_count;
    if (zc > 4096) zc = 4096;
    long total = (long)zc * 2304;
    for (long i = (long)blockIdx.x * blockDim.x + threadIdx.x; i < total;
         i += (long)gridDim.x * blockDim.x) {
        int z = (int)(i / 2304);
        int q = (int)(i % 2304);
        int o = q / 9, tap = q % 9;
        int li = g_xz_list[z];
        int pix = li % PIX;
        int ch = (li / PIX) & 255;
        int n = li / (PIX * C_);
        int h = pix / HW_, wv = pix % HW_;
        int kh = tap / 3, kw = tap % 3;
        int oh = h + 1 - kh, ow = wv + 1 - kw;
        if ((unsigned)oh < HW_ && (unsigned)ow < HW_) {
            float bw = (float)g_wb[((size_t)tap * O_ + o) * C_ + ch];
            atomicAdd(&out[((size_t)(n * O_ + o)) * PIX + oh * HW_ + ow],
                      -bw * alpha_of(n) * g_m[o]);
        }
    }
}

// ---------------- K5: exact correction for w==0 ----------------
__global__ void k_wzero(const float* __restrict__ x, float* __restrict__ out) {
    int zc = g_wz_count;
    if (zc > 64) zc = 64;
    long total = (long)zc * N_ * PIX;
    for (long i = (long)blockIdx.x * blockDim.x + threadIdx.x; i < total;
         i += (long)gridDim.x * blockDim.x) {
        int z = (int)(i / ((long)N_ * PIX));
        int rte = (int)(i % ((long)N_ * PIX));
        int n = rte / PIX, pix = rte % PIX;
        int oh = pix / HW_, ow = pix % HW_;
        int li = g_wz_list[z];
        int tap = li % 9;
        int ch = (li / 9) & 255;
        int o = li / (9 * C_);
        int kh = tap / 3, kw = tap % 3;
        int ih = oh - 1 + kh, iw = ow - 1 + kw;
        if ((unsigned)ih < HW_ && (unsigned)iw < HW_) {
            float xv = x[((size_t)(n * C_ + ch)) * PIX + ih * HW_ + iw];
            if (xv != 0.f) {
                float bx = (xv < 0.f) ? -1.f : 1.f;
                atomicAdd(&out[((size_t)(n * O_ + o)) * PIX + pix],
                          -bx * alpha_of(n) * g_m[o]);
            }
        }
    }
}

// ---------------- launch ----------------
extern "C" void kernel_launch(void* const* d_in, const int* in_sizes, int n_in,
                              void* d_out, int out_size) {
    const float* x = (const float*)d_in[0];
    const float* w = (const float*)d_in[1];
    float* out = (float*)d_out;

    cudaFuncSetAttribute(k_conv, cudaFuncAttributeMaxDynamicSharedMemorySize, CONV_SMEM);

    k_zero<<<9, 256>>>();
    k_packx<<<416, 256>>>(x);
    k_packw<<<256, 256>>>(w);
    k_conv<<<3136, 256, CONV_SMEM>>>(out);
    k_xzero<<<64, 256>>>(out);
    k_wzero<<<128, 256>>>(x, out);
}

// round 13
// speedup vs baseline: 1.0032x; 1.0032x over previous
#include <cuda_runtime.h>
#include <cstdint>

#define N_   32
#define C_   256
#define O_   256
#define HW_  56
#define PIX  3136
#define NPIX (N_ * PIX)          // 100352 = 784 * 128
#define CNTS 802816.0f
#define EPSF 1e-5f

// ---------------- device scratch ----------------
__device__ float g_asum[N_];
__device__ float g_m[O_];
__device__ __align__(16) signed char g_xb[(size_t)NPIX * C_];     // int8 +-1 [pix][c]
__device__ __align__(16) signed char g_wb[9 * O_ * C_];           // int8 +-1 [tap][o][c]
__device__ __align__(16) unsigned g_xbits[(size_t)NPIX * 8];      // bitpacked [pix][8w]
__device__ __align__(16) unsigned g_wt[9 * 8 * O_];               // bitpacked [tap][w8][o]
__device__ int g_pw[O_ * 9];
__device__ int g_xz_count;
__device__ int g_wz_count;
__device__ int g_xz_list[4096];
__device__ int g_wz_list[64];

__device__ __forceinline__ float alpha_of(int n) {
    return fmaxf(2.f * g_asum[n] / CNTS, EPSF);
}

__device__ __forceinline__ uint32_t s2u(const void* p) {
    uint32_t a;
    asm("{ .reg .u64 t; cvta.to.shared.u64 t, %1; cvt.u32.u64 %0, t; }" : "=r"(a) : "l"(p));
    return a;
}
__device__ __forceinline__ void cpa16(uint32_t dst, const void* src, unsigned srcsz) {
    asm volatile("cp.async.cg.shared.global [%0], [%1], 16, %2;"
                 :: "r"(dst), "l"(src), "r"(srcsz) : "memory");
}
__device__ __forceinline__ void cpa_wait_all() {
    asm volatile("cp.async.commit_group;\ncp.async.wait_group 0;" ::: "memory");
}

__device__ __forceinline__ void imma16832(int* c, const unsigned* a, const unsigned* b) {
    asm volatile(
        "mma.sync.aligned.m16n8k32.row.col.s32.s8.s8.s32 "
        "{%0,%1,%2,%3}, {%4,%5,%6,%7}, {%8,%9}, {%0,%1,%2,%3};"
        : "+r"(c[0]), "+r"(c[1]), "+r"(c[2]), "+r"(c[3])
        : "r"(a[0]), "r"(a[1]), "r"(a[2]), "r"(a[3]), "r"(b[0]), "r"(b[1]));
}

// ---------------- K0: zero everything ----------------
__global__ void k_zero() {
    int t = blockIdx.x * blockDim.x + threadIdx.x;
    if (t < N_) g_asum[t] = 0.f;
    if (t < O_ * 9) g_pw[t] = 0;
    if (t == 0) { g_xz_count = 0; g_wz_count = 0; }
}

// ---------------- K1: pack x -> int8 +-1 NHWC, bitpacked, sum|x|, zero list ----------
__global__ void k_packx(const float* __restrict__ x) {
    int b   = blockIdx.x;
    int n   = b & 31;
    int pix = (b >> 5) * 256 + threadIdx.x;
    int tid = threadIdx.x;

    float s = 0.f;
    if (pix < PIX) {
        const float* base = x + (size_t)n * C_ * PIX + pix;
        signed char* dst = &g_xb[((size_t)n * PIX + pix) * C_];
        unsigned bw[8];
#pragma unroll
        for (int w8 = 0; w8 < 8; w8++) {
            unsigned bb = 0;
            signed char u[32];
#pragma unroll
            for (int j = 0; j < 32; j++) {
                int ch = w8 * 32 + j;
                float v = base[(size_t)ch * PIX];
                s += fabsf(v);
                bool neg = (v < 0.f);
                u[j] = neg ? (signed char)-1 : (signed char)1;
                bb |= ((unsigned)neg) << j;
                if (v == 0.f) {
                    int idx = atomicAdd(&g_xz_count, 1);
                    if (idx < 4096) g_xz_list[idx] = (n * C_ + ch) * PIX + pix;
                }
            }
            bw[w8] = bb;
            *(uint4*)&dst[w8 * 32]      = *(const uint4*)&u[0];
            *(uint4*)&dst[w8 * 32 + 16] = *(const uint4*)&u[16];
        }
        uint4* bd = (uint4*)&g_xbits[((size_t)n * PIX + pix) * 8];
        bd[0] = make_uint4(bw[0], bw[1], bw[2], bw[3]);
        bd[1] = make_uint4(bw[4], bw[5], bw[6], bw[7]);
    }

    __shared__ float red[256];
    red[tid] = s;
    __syncthreads();
    for (int st = 128; st > 0; st >>= 1) {
        if (tid < st) red[tid] += red[tid + st];
        __syncthreads();
    }
    if (tid == 0) atomicAdd(&g_asum[n], red[0]);
}

// ---------------- K2: pack w ----------------
__global__ void k_packw(const float* __restrict__ w) {
    int o = blockIdx.x;
    int tid = threadIdx.x;
    int j = tid >> 5, lane = tid & 31;
    int c = j * 32 + lane;

    float s = 0.f;
#pragma unroll
    for (int tap = 0; tap < 9; tap++) {
        float v = w[((size_t)(o * C_ + c)) * 9 + tap];
        s += fabsf(v);
        bool neg = (v < 0.f);
        g_wb[((size_t)tap * O_ + o) * C_ + c] = neg ? (signed char)-1 : (signed char)1;
        unsigned bal = __ballot_sync(0xffffffffu, neg);
        if (lane == 0) {
            g_wt[(tap * 8 + j) * O_ + o] = bal;
            atomicAdd(&g_pw[o * 9 + tap], __popc(bal));
        }
        if (v == 0.f) {
            int idx = atomicAdd(&g_wz_count, 1);
            if (idx < 64) g_wz_list[idx] = (o * C_ + c) * 9 + tap;
        }
    }
    __shared__ float red[256];
    red[tid] = s;
    __syncthreads();
    for (int st = 128; st > 0; st >>= 1) {
        if (tid < st) red[tid] += red[tid + st];
        __syncthreads();
    }
    if (tid == 0) g_m[o] = red[0] / 2304.f;
}

// ---------------- K3: INTERLEAVED hybrid conv (3 CTAs/SM) ----------------
// CTA 128(M) x 64(N); grid = 784 * 4 = 3136; 256 thr, 8 warps (2Mx4N).
// Tensor: taps 0,1 (cp.async zero-fill halo). Popcount: taps 2..8, packed pacc2.
#define RS8     36
#define B8_OFF  (128 * RS8)                 // 4608
#define XB_OFF  (B8_OFF + 64 * RS8)         // 6912
#define WB_OFF  (XB_OFF + 7 * 8 * 128)      // 14080
#define CONV_SMEM ((WB_OFF + 7 * 8 * 64) * 4)  // 70656 B

__global__ __launch_bounds__(256, 3) void k_conv(float* __restrict__ out) {
    extern __shared__ unsigned smw[];

    int tid  = threadIdx.x;
    int wid  = tid >> 5;
    int lane = tid & 31;
    int g    = lane >> 2;
    int tig  = lane & 3;

    int mBase = (blockIdx.x >> 2) * 128;
    int nBase = (blockIdx.x & 3) * 64;

    int m_off = (wid & 1) * 64;
    int n_off = (wid >> 1) * 16;

    int acc[4][2][4];        // IMMA accumulators (taps 0,1)
    unsigned pacc2[4][2][2]; // packed popcount: [0]=k0|k1<<16, [1]=k2|k3<<16
#pragma unroll
    for (int mi = 0; mi < 4; mi++)
#pragma unroll
        for (int ni = 0; ni < 2; ni++) {
#pragma unroll
            for (int k = 0; k < 4; k++) acc[mi][ni][k] = 0;
            pacc2[mi][ni][0] = 0; pacc2[mi][ni][1] = 0;
        }

    const uint4 z4 = make_uint4(0u, 0u, 0u, 0u);
    const uint32_t sbase = s2u(smw);

    // ---- one-time fill of bitpacked tiles (taps 2..8) ----
    for (int u = tid; u < 7 * 128; u += 256) {
        int t7 = u >> 7, row = u & 127;
        int tap = t7 + 2;
        int gp = mBase + row;
        int fn = gp / PIX;
        int fp = gp - fn * PIX;
        int fh = fp / HW_, fw = fp - (fp / HW_) * HW_;
        int h2 = fh + tap / 3 - 1, w2 = fw + tap % 3 - 1;
        uint4 lo = z4, hi = z4;
        if ((unsigned)h2 < HW_ && (unsigned)w2 < HW_) {
            const uint4* src = (const uint4*)&g_xbits[((size_t)fn * PIX + h2 * HW_ + w2) * 8];
            lo = src[0]; hi = src[1];
        }
        unsigned* d = &smw[XB_OFF + t7 * 1024 + row];
        d[0] = lo.x; d[128] = lo.y; d[256] = lo.z; d[384] = lo.w;
        d[512] = hi.x; d[640] = hi.y; d[768] = hi.z; d[896] = hi.w;
    }
    for (int v = tid; v < 7 * 8 * 16; v += 256) {   // 896 uint4
        int q = v >> 4;
        int c4 = (v & 15) * 4;
        int t7 = q >> 3, j = q & 7;
        *(uint4*)&smw[WB_OFF + q * 64 + c4] =
            *(const uint4*)&g_wt[((t7 + 2) * 8 + j) * O_ + nBase + c4];
    }

    // fill-role mapping for int8 A tile
    int pix_i = tid >> 1;
    int half  = tid & 1;
    int gp = mBase + pix_i;
    int fn = gp / PIX;
    int fp = gp - fn * PIX;
    int fh = fp / HW_, fw = fp - (fp / HW_) * HW_;

    int pu = 0;   // popcount unit cursor 0..55

#pragma unroll 1
    for (int tt = 0; tt < 2; tt++) {
        int h2 = fh - 1, w2 = fw + tt - 1;
        bool valid = ((unsigned)h2 < HW_) && ((unsigned)w2 < HW_);
        unsigned asz = valid ? 16u : 0u;
        const signed char* srcA = &g_xb[((size_t)fn * PIX + h2 * HW_ + w2) * C_];
#pragma unroll 1
        for (int hf = 0; hf < 2; hf++) {
            __syncthreads();
            {
                // A: 128 rows x 128B via cp.async (zero-fill on halo)
                uint32_t dA = sbase + (pix_i * RS8 + half * 16) * 4;
                const signed char* sA = srcA + hf * 128 + half * 64;
#pragma unroll
                for (int j2 = 0; j2 < 4; j2++)
                    cpa16(dA + j2 * 16, sA + j2 * 16, asz);
                // B: 64 rows x 128B via cp.async
                if (tid < 128) {
                    int row = tid >> 1, bh = tid & 1;
                    uint32_t dB = sbase + (B8_OFF + row * RS8 + bh * 16) * 4;
                    const signed char* sB = &g_wb[((size_t)tt * O_ + nBase + row) * C_ + hf * 128 + bh * 64];
#pragma unroll
                    for (int j2 = 0; j2 < 4; j2++)
                        cpa16(dB + j2 * 16, sB + j2 * 16, 16u);
                }
            }
            cpa_wait_all();
            __syncthreads();

#pragma unroll 1
            for (int kc = 0; kc < 4; kc++) {
                // ---- 8 IMMA ----
                unsigned a[4][4], bfr[2][2];
                int kw0 = kc * 8 + tig;
#pragma unroll
                for (int mi = 0; mi < 4; mi++) {
                    int base = (m_off + mi * 16 + g) * RS8 + kw0;
                    a[mi][0] = smw[base];
                    a[mi][1] = smw[base + 8 * RS8];
                    a[mi][2] = smw[base + 4];
                    a[mi][3] = smw[base + 8 * RS8 + 4];
                }
#pragma unroll
                for (int ni = 0; ni < 2; ni++) {
                    int base = B8_OFF + (n_off + ni * 8 + g) * RS8 + kw0;
                    bfr[ni][0] = smw[base];
                    bfr[ni][1] = smw[base + 4];
                }
#pragma unroll
                for (int mi = 0; mi < 4; mi++)
#pragma unroll
                    for (int ni = 0; ni < 2; ni++)
                        imma16832(acc[mi][ni], a[mi], bfr[ni]);

                // ---- 3-4 popcount units interleaved ----
                int nu = (kc < 2) ? 4 : 3;
#pragma unroll 1
                for (int q = 0; q < nu; q++) {
                    const unsigned* xb = &smw[XB_OFF + pu * 128];
                    const unsigned* wb = &smw[WB_OFF + pu * 64];
                    unsigned xr[8], wc[4];
#pragma unroll
                    for (int mi = 0; mi < 4; mi++) {
                        xr[mi * 2]     = xb[m_off + mi * 16 + g];
                        xr[mi * 2 + 1] = xb[m_off + mi * 16 + 8 + g];
                    }
#pragma unroll
                    for (int ni = 0; ni < 2; ni++) {
                        wc[ni * 2]     = wb[n_off + ni * 8 + tig * 2];
                        wc[ni * 2 + 1] = wb[n_off + ni * 8 + tig * 2 + 1];
                    }
#pragma unroll
                    for (int mi = 0; mi < 4; mi++)
#pragma unroll
                        for (int ni = 0; ni < 2; ni++) {
                            unsigned p0 = __popc(xr[mi * 2]     ^ wc[ni * 2]);
                            unsigned p1 = __popc(xr[mi * 2]     ^ wc[ni * 2 + 1]);
                            unsigned p2 = __popc(xr[mi * 2 + 1] ^ wc[ni * 2]);
                            unsigned p3 = __popc(xr[mi * 2 + 1] ^ wc[ni * 2 + 1]);
                            pacc2[mi][ni][0] += p0 + (p1 << 16);
                            pacc2[mi][ni][1] += p2 + (p3 << 16);
                        }
                    pu++;
                }
            }
        }
    }

    // ---- epilogue: merge, pad-correct (taps 2..8), scale, store ----
#pragma unroll
    for (int mi = 0; mi < 4; mi++) {
#pragma unroll
        for (int h = 0; h < 2; h++) {
            int row = m_off + mi * 16 + h * 8 + g;
            int gpp = mBase + row;
            int n = gpp / PIX;
            int p = gpp - n * PIX;
            int oh = p / HW_, ow = p - (p / HW_) * HW_;
            float al = alpha_of(n);
            bool top = (oh == 0), bot = (oh == HW_ - 1);
            bool lef = (ow == 0), rig = (ow == HW_ - 1);
            bool edge = top || bot || lef || rig;
            float* ob = out + (size_t)n * O_ * PIX + p;
#pragma unroll
            for (int ni = 0; ni < 2; ni++) {
#pragma unroll
                for (int j = 0; j < 2; j++) {
                    int o = nBase + n_off + ni * 8 + tig * 2 + j;
                    unsigned pp = pacc2[mi][ni][h];
                    int pv = (j == 0) ? (int)(pp & 0xFFFFu) : (int)(pp >> 16);
                    int S = acc[mi][ni][h * 2 + j] + 1792 - 2 * pv;
                    if (edge) {
                        const int* pwo = &g_pw[o * 9];
                        if (top || rig) S -= 256 - 2 * __ldg(pwo + 2);
                        if (lef)        S -= 256 - 2 * __ldg(pwo + 3);
                        if (rig)        S -= 256 - 2 * __ldg(pwo + 5);
                        if (bot || lef) S -= 256 - 2 * __ldg(pwo + 6);
                        if (bot)        S -= 256 - 2 * __ldg(pwo + 7);
                        if (bot || rig) S -= 256 - 2 * __ldg(pwo + 8);
                    }
                    ob[(size_t)o * PIX] = al * __ldg(&g_m[o]) * (float)S;
                }
            }
        }
    }
}

// ---------------- K4: exact correction for x==0 ----------------
__global__ void k_xzero(float* __restrict__ out) {
    int zc = g_xz_count;
    if (zc > 4096) zc = 4096;
    long total = (long)zc * 2304;
    for (long i = (long)blockIdx.x * blockDim.x + threadIdx.x; i < total;
         i += (long)gridDim.x * blockDim.x) {
        int z = (int)(i / 2304);
        int q = (int)(i % 2304);
        int o = q / 9, tap = q % 9;
        int li = g_xz_list[z];
        int pix = li % PIX;
        int ch = (li / PIX) & 255;
        int n = li / (PIX * C_);
        int h = pix / HW_, wv = pix % HW_;
        int kh = tap / 3, kw = tap % 3;
        int oh = h + 1 - kh, ow = wv + 1 - kw;
        if ((unsigned)oh < HW_ && (unsigned)ow < HW_) {
            float bw = (float)g_wb[((size_t)tap * O_ + o) * C_ + ch];
            atomicAdd(&out[((size_t)(n * O_ + o)) * PIX + oh * HW_ + ow],
                      -bw * alpha_of(n) * g_m[o]);
        }
    }
}

// ---------------- K5: exact correction for w==0 ----------------
__global__ void k_wzero(const float* __restrict__ x, float* __restrict__ out) {
    int zc = g_wz_count;
    if (zc > 64) zc = 64;
    long total = (long)zc * N_ * PIX;
    for (long i = (long)blockIdx.x * blockDim.x + threadIdx.x; i < total;
         i += (long)gridDim.x * blockDim.x) {
        int z = (int)(i / ((long)N_ * PIX));
        int rte = (int)(i % ((long)N_ * PIX));
        int n = rte / PIX, pix = rte % PIX;
        int oh = pix / HW_, ow = pix % HW_;
        int li = g_wz_list[z];
        int tap = li % 9;
        int ch = (li / 9) & 255;
        int o = li / (9 * C_);
        int kh = tap / 3, kw = tap % 3;
        int ih = oh - 1 + kh, iw = ow - 1 + kw;
        if ((unsigned)ih < HW_ && (unsigned)iw < HW_) {
            float xv = x[((size_t)(n * C_ + ch)) * PIX + ih * HW_ + iw];
            if (xv != 0.f) {
                float bx = (xv < 0.f) ? -1.f : 1.f;
                atomicAdd(&out[((size_t)(n * O_ + o)) * PIX + pix],
                          -bx * alpha_of(n) * g_m[o]);
            }
        }
    }
}

// ---------------- launch ----------------
extern "C" void kernel_launch(void* const* d_in, const int* in_sizes, int n_in,
                              void* d_out, int out_size) {
    const float* x = (const float*)d_in[0];
    const float* w = (const float*)d_in[1];
    float* out = (float*)d_out;

    cudaFuncSetAttribute(k_conv, cudaFuncAttributeMaxDynamicSharedMemorySize, CONV_SMEM);

    k_zero<<<9, 256>>>();
    k_packx<<<416, 256>>>(x);
    k_packw<<<256, 256>>>(w);
    k_conv<<<3136, 256, CONV_SMEM>>>(out);
    k_xzero<<<64, 256>>>(out);
    k_wzero<<<128, 256>>>(x, out);
}